// round 3
// baseline (speedup 1.0000x reference)
#include <cuda_runtime.h>
#include <math.h>

// Problem constants
#define GRID_SZ 14
#define L_SEQ   197           // 14*14 + 1
#define NH      12
#define DK      64
#define D_MODEL 768
#define BATCH   32
#define M_ROWS  (BATCH * L_SEQ)   // 6304
#define TOPK    32
#define N_ROWS_TOT (BATCH * NH * L_SEQ)  // 75648

// Scratch (device globals: no allocation allowed)
__device__ float g_Q[M_ROWS * D_MODEL];
__device__ float g_K[M_ROWS * D_MODEL];
__device__ float g_V[M_ROWS * D_MODEL];
__device__ float g_C[M_ROWS * D_MODEL];   // consensus (attention output before W_o)

// ---------------------------------------------------------------------------
// SGEMM body:  C[M x 768] = A[M x 768] @ B[768 x 768] + bias
// Classic 128x128 tile, BK=8, 256 threads, 8x8 per-thread microtile.
// ---------------------------------------------------------------------------
#define BM 128
#define BN 128
#define BK 8

__device__ __forceinline__ void sgemm_body(
    const float* __restrict__ A,
    const float* __restrict__ Bw, const float* __restrict__ bias,
    float* __restrict__ C, int M)
{
    __shared__ float As[BK][BM];
    __shared__ float Bs[BK][BN];

    int bm = blockIdx.y, bn = blockIdx.x;
    int tid = threadIdx.x;
    int tx = tid & 15;       // 0..15  (N dir)
    int ty = tid >> 4;       // 0..15  (M dir)

    float acc[8][8];
#pragma unroll
    for (int i = 0; i < 8; i++)
#pragma unroll
        for (int j = 0; j < 8; j++) acc[i][j] = 0.f;

    int row0 = bm * BM;
    int col0 = bn * BN;

    int a_m = (tid * 4) / BK;   // 0..127
    int a_k = (tid * 4) % BK;   // 0 or 4
    int b_r = (tid * 4) / BN;   // 0..7
    int b_c = (tid * 4) % BN;   // 0..124 step 4

    for (int kt = 0; kt < D_MODEL; kt += BK) {
        float4 av = make_float4(0.f, 0.f, 0.f, 0.f);
        int gm = row0 + a_m;
        if (gm < M)
            av = *reinterpret_cast<const float4*>(&A[(size_t)gm * D_MODEL + kt + a_k]);
        As[a_k + 0][a_m] = av.x;
        As[a_k + 1][a_m] = av.y;
        As[a_k + 2][a_m] = av.z;
        As[a_k + 3][a_m] = av.w;

        float4 bv = *reinterpret_cast<const float4*>(&Bw[(size_t)(kt + b_r) * D_MODEL + col0 + b_c]);
        *reinterpret_cast<float4*>(&Bs[b_r][b_c]) = bv;

        __syncthreads();

#pragma unroll
        for (int k = 0; k < BK; k++) {
            float ra[8], rb[8];
#pragma unroll
            for (int i = 0; i < 4; i++) {
                ra[i]     = As[k][ty * 4 + i];
                ra[i + 4] = As[k][64 + ty * 4 + i];
            }
#pragma unroll
            for (int j = 0; j < 4; j++) {
                rb[j]     = Bs[k][tx * 4 + j];
                rb[j + 4] = Bs[k][64 + tx * 4 + j];
            }
#pragma unroll
            for (int i = 0; i < 8; i++)
#pragma unroll
                for (int j = 0; j < 8; j++)
                    acc[i][j] = fmaf(ra[i], rb[j], acc[i][j]);
        }
        __syncthreads();
    }

#pragma unroll
    for (int i = 0; i < 8; i++) {
        int m = row0 + ((i < 4) ? (ty * 4 + i) : (64 + ty * 4 + (i - 4)));
        if (m >= M) continue;
#pragma unroll
        for (int j = 0; j < 8; j++) {
            int n = col0 + ((j < 4) ? (tx * 4 + j) : (64 + tx * 4 + (j - 4)));
            C[(size_t)m * D_MODEL + n] = acc[i][j] + bias[n];
        }
    }
}

// Fused Q/K/V projections: blockIdx.z selects which weight/bias/output.
__global__ __launch_bounds__(256) void sgemm_qkv(
    const float* __restrict__ x,
    const float* __restrict__ Wq, const float* __restrict__ bq,
    const float* __restrict__ Wk, const float* __restrict__ bk,
    const float* __restrict__ Wv, const float* __restrict__ bv)
{
    int z = blockIdx.z;
    const float* W = (z == 0) ? Wq : (z == 1) ? Wk : Wv;
    const float* b = (z == 0) ? bq : (z == 1) ? bk : bv;
    float* C = (z == 0) ? g_Q : (z == 1) ? g_K : g_V;
    sgemm_body(x, W, b, C, M_ROWS);
}

// Output projection: out = g_C @ W_o + b_o
__global__ __launch_bounds__(256) void sgemm_out(
    const float* __restrict__ Wo, const float* __restrict__ bo,
    float* __restrict__ out)
{
    sgemm_body(g_C, Wo, bo, out, M_ROWS);
}

// ---------------------------------------------------------------------------
// Attention kernel: one warp per (b, h, i) row; ONE LANE PER CANDIDATE.
//   - i >= 1: <=26 valid columns (CLS + Chebyshev<=2 neighbors); each lane
//     accumulates its candidate's 64-dim dist^2 privately (no shuffles).
//   - i == 0: 197 valid columns; true top-32 with lowest-index tie-break.
// Writes dense weights + mask rows (zeros elsewhere) and consensus = w @ V.
// ---------------------------------------------------------------------------
__global__ __launch_bounds__(256) void attn_kernel(
    const float* __restrict__ log_sigma,
    float* __restrict__ w_out, float* __restrict__ m_out)
{
    __shared__ __align__(16) float q_sh[8][DK];
    __shared__ float w_sh[8][32];
    __shared__ int   c_sh[8][32];

    int warp = threadIdx.x >> 5;
    int lane = threadIdx.x & 31;
    int rowid = blockIdx.x * 8 + warp;
    if (rowid >= N_ROWS_TOT) return;

    int b   = rowid / (NH * L_SEQ);
    int rem = rowid % (NH * L_SEQ);
    int h   = rem / L_SEQ;
    int i   = rem % L_SEQ;

    float inv = -0.5f * expf(-2.f * log_sigma[0]);   // -0.5 / sigma^2

    const float* qp = g_Q + (size_t)(b * L_SEQ + i) * D_MODEL + h * DK;
    q_sh[warp][lane]      = qp[lane];
    q_sh[warp][lane + 32] = qp[lane + 32];
    __syncwarp();

    float myScore = -INFINITY;
    int   myCol   = 0;
    int   nj;
    bool  act;

    if (i > 0) {
        // Each lane owns one candidate: lane 0 -> CLS, lanes 1.. -> box cells.
        int p = i - 1, r = p / GRID_SZ, c = p % GRID_SZ;
        int r0 = (r - 2 < 0) ? 0 : r - 2;
        int r1 = (r + 2 > GRID_SZ - 1) ? GRID_SZ - 1 : r + 2;
        int c0 = (c - 2 < 0) ? 0 : c - 2;
        int c1 = (c + 2 > GRID_SZ - 1) ? GRID_SZ - 1 : c + 2;
        int wbox = c1 - c0 + 1;
        int hbox = r1 - r0 + 1;
        nj  = 1 + wbox * hbox;
        act = lane < nj;

        int j = 0;
        if (act && lane > 0) {
            int idx = lane - 1;
            j = 1 + (r0 + idx / wbox) * GRID_SZ + (c0 + idx % wbox);
        }

        if (act) {
            const float4* kp4 = reinterpret_cast<const float4*>(
                g_K + (size_t)(b * L_SEQ + j) * D_MODEL + h * DK);
            const float4* qp4 = reinterpret_cast<const float4*>(q_sh[warp]);
            float acc = 0.f;
#pragma unroll
            for (int d = 0; d < 16; d++) {
                float4 kk = kp4[d];
                float4 qq = qp4[d];
                float dx = qq.x - kk.x, dy = qq.y - kk.y;
                float dz = qq.z - kk.z, dw = qq.w - kk.w;
                acc = fmaf(dx, dx, acc);
                acc = fmaf(dy, dy, acc);
                acc = fmaf(dz, dz, acc);
                acc = fmaf(dw, dw, acc);
            }
            myScore = inv * acc;
            myCol   = j;
        }
    } else {
        // CLS row: 197 candidates, true top-32 (lowest-index tie-break).
        float sc[7];
#pragma unroll
        for (int s = 0; s < 7; s++) {
            int j = s * 32 + lane;
            if (j < L_SEQ) {
                const float4* kp4 = reinterpret_cast<const float4*>(
                    g_K + (size_t)(b * L_SEQ + j) * D_MODEL + h * DK);
                const float4* qp4 = reinterpret_cast<const float4*>(q_sh[warp]);
                float acc = 0.f;
#pragma unroll
                for (int d = 0; d < 16; d++) {
                    float4 kk = kp4[d];
                    float4 qq = qp4[d];
                    float dx = qq.x - kk.x, dy = qq.y - kk.y;
                    float dz = qq.z - kk.z, dw = qq.w - kk.w;
                    acc = fmaf(dx, dx, acc);
                    acc = fmaf(dy, dy, acc);
                    acc = fmaf(dz, dz, acc);
                    acc = fmaf(dw, dw, acc);
                }
                sc[s] = inv * acc;
            } else {
                sc[s] = -INFINITY;
            }
        }

        unsigned used = 0;
        for (int t = 0; t < TOPK; t++) {
            float bv = -INFINITY;
            int   bj = 0x7fffffff;
#pragma unroll
            for (int s = 0; s < 7; s++) {
                if (!((used >> s) & 1u)) {
                    int j = s * 32 + lane;
                    if (sc[s] > bv || (sc[s] == bv && j < bj)) { bv = sc[s]; bj = j; }
                }
            }
#pragma unroll
            for (int o = 16; o > 0; o >>= 1) {
                float ov = __shfl_xor_sync(0xffffffffu, bv, o);
                int   oj = __shfl_xor_sync(0xffffffffu, bj, o);
                if (ov > bv || (ov == bv && oj < bj)) { bv = ov; bj = oj; }
            }
            if (lane == (bj & 31)) used |= 1u << (bj >> 5);  // mark winner consumed
            if (lane == t) { myScore = bv; myCol = bj; }
        }
        nj  = TOPK;
        act = true;
    }

    // Zero-fill dense rows (coalesced)
    float* wrow = w_out + (size_t)rowid * L_SEQ;
    float* mrow = m_out + (size_t)rowid * L_SEQ;
#pragma unroll
    for (int t = lane; t < L_SEQ; t += 32) { wrow[t] = 0.f; mrow[t] = 0.f; }

    // Softmax over active lanes
    float v  = act ? myScore : -INFINITY;
    float mx = v;
#pragma unroll
    for (int o = 16; o > 0; o >>= 1)
        mx = fmaxf(mx, __shfl_xor_sync(0xffffffffu, mx, o));
    float e  = act ? expf(myScore - mx) : 0.f;
    float se = e;
#pragma unroll
    for (int o = 16; o > 0; o >>= 1)
        se += __shfl_xor_sync(0xffffffffu, se, o);
    float w = e / se;

    // Stash weights/cols for consensus; order zero-stores before scatter.
    w_sh[warp][lane] = act ? w : 0.f;
    c_sh[warp][lane] = act ? myCol : 0;
    __syncwarp();

    if (act) {
        wrow[myCol] = w;
        mrow[myCol] = (w > 1e-6f) ? 1.f : 0.f;
    }

    // Consensus: sum_j w_j * V[b,h,j,:]  (lanes index the head dim)
    float a0 = 0.f, a1 = 0.f;
    const float* vbase = g_V + (size_t)b * L_SEQ * D_MODEL + h * DK;
#pragma unroll 4
    for (int t = 0; t < nj; t++) {
        float wv  = w_sh[warp][t];
        int   col = c_sh[warp][t];
        const float* vp = vbase + (size_t)col * D_MODEL;
        a0 = fmaf(wv, vp[lane], a0);
        a1 = fmaf(wv, vp[lane + 32], a1);
    }
    float* cp = g_C + (size_t)(b * L_SEQ + i) * D_MODEL + h * DK;
    cp[lane]      = a0;
    cp[lane + 32] = a1;
}

// ---------------------------------------------------------------------------
extern "C" void kernel_launch(void* const* d_in, const int* in_sizes, int n_in,
                              void* d_out, int out_size)
{
    const float* x  = (const float*)d_in[0];
    const float* Wq = (const float*)d_in[1];
    const float* bq = (const float*)d_in[2];
    const float* Wk = (const float*)d_in[3];
    const float* bk = (const float*)d_in[4];
    const float* Wv = (const float*)d_in[5];
    const float* bv = (const float*)d_in[6];
    const float* Wo = (const float*)d_in[7];
    const float* bo = (const float*)d_in[8];
    const float* ls = (const float*)d_in[9];

    float* out   = (float*)d_out;                                    // (B, L, D)
    float* w_out = out + (size_t)M_ROWS * D_MODEL;                   // (B, H, L, L)
    float* m_out = w_out + (size_t)BATCH * NH * L_SEQ * L_SEQ;       // (B, H, L, L)

    // Fused QKV projections: 900 blocks -> better wave packing than 3x300.
    dim3 qkv_grid(D_MODEL / BN, (M_ROWS + BM - 1) / BM, 3);   // (6, 50, 3)
    sgemm_qkv<<<qkv_grid, 256>>>(x, Wq, bq, Wk, bk, Wv, bv);

    // Attention (scores + topk + softmax + weights/mask + consensus)
    int nblk = (N_ROWS_TOT + 7) / 8;
    attn_kernel<<<nblk, 256>>>(ls, w_out, m_out);

    // Output projection
    dim3 ogrid(D_MODEL / BN, (M_ROWS + BM - 1) / BM);         // (6, 50)
    sgemm_out<<<ogrid, 256>>>(Wo, bo, out);
}

// round 5
// speedup vs baseline: 1.6531x; 1.6531x over previous
#include <cuda_runtime.h>
#include <math.h>

// Problem constants
#define GRID_SZ 14
#define L_SEQ   197           // 14*14 + 1
#define NH      12
#define DK      64
#define D_MODEL 768
#define BATCH   32
#define M_ROWS  (BATCH * L_SEQ)   // 6304
#define TOPK    32
#define N_ROWS_TOT (BATCH * NH * L_SEQ)  // 75648

// Scratch (device globals: no allocation allowed)
__device__ float g_Q[M_ROWS * D_MODEL];
__device__ float g_K[M_ROWS * D_MODEL];
__device__ float g_V[M_ROWS * D_MODEL];
__device__ float g_C[M_ROWS * D_MODEL];   // consensus (attention output before W_o)

// ---------------------------------------------------------------------------
// SGEMM:  C[M x 768] = A[M x 768] @ B[768 x 768] + bias
// 128x128 tile, BK=8, 256 threads, 8x8 microtile.
// float4 LDS + register prefetch of next global tile.
// ---------------------------------------------------------------------------
#define BM 128
#define BN 128
#define BK 8

__global__ __launch_bounds__(256) void sgemm_bias(
    const float* __restrict__ A_ext, int a_sel,
    const float* __restrict__ Bw, const float* __restrict__ bias,
    float* __restrict__ C_ext, int c_sel, int M)
{
    const float* A = (a_sel == 0) ? A_ext : g_C;
    float* C = (c_sel == 0) ? g_Q : (c_sel == 1) ? g_K : (c_sel == 2) ? g_V : C_ext;

    __shared__ __align__(16) float As[BK][BM];
    __shared__ __align__(16) float Bs[BK][BN];

    int bm = blockIdx.y, bn = blockIdx.x;
    int tid = threadIdx.x;
    int tx = tid & 15;       // 0..15  (N dir)
    int ty = tid >> 4;       // 0..15  (M dir)

    float acc[8][8];
#pragma unroll
    for (int i = 0; i < 8; i++)
#pragma unroll
        for (int j = 0; j < 8; j++) acc[i][j] = 0.f;

    int row0 = bm * BM;
    int col0 = bn * BN;

    int a_m = (tid * 4) / BK;   // 0..127
    int a_k = (tid * 4) % BK;   // 0 or 4
    int b_r = (tid * 4) / BN;   // 0..7
    int b_c = (tid * 4) % BN;   // 0..124 step 4

    const int gm = row0 + a_m;
    const bool a_ok = (gm < M);
    const float* Aptr = &A[(size_t)gm * D_MODEL + a_k];
    const float* Bptr = &Bw[(size_t)b_r * D_MODEL + col0 + b_c];

    // Prefetch first tile
    float4 av = make_float4(0.f, 0.f, 0.f, 0.f);
    if (a_ok) av = *reinterpret_cast<const float4*>(Aptr);
    float4 bv = *reinterpret_cast<const float4*>(Bptr);

    for (int kt = 0; kt < D_MODEL; kt += BK) {
        As[a_k + 0][a_m] = av.x;
        As[a_k + 1][a_m] = av.y;
        As[a_k + 2][a_m] = av.z;
        As[a_k + 3][a_m] = av.w;
        *reinterpret_cast<float4*>(&Bs[b_r][b_c]) = bv;
        __syncthreads();

        // Prefetch next tile into registers while computing this one
        if (kt + BK < D_MODEL) {
            if (a_ok) av = *reinterpret_cast<const float4*>(Aptr + kt + BK);
            bv = *reinterpret_cast<const float4*>(Bptr + (size_t)(kt + BK) * D_MODEL);
        }

#pragma unroll
        for (int k = 0; k < BK; k++) {
            float ra[8], rb[8];
            *reinterpret_cast<float4*>(&ra[0]) = *reinterpret_cast<const float4*>(&As[k][ty * 4]);
            *reinterpret_cast<float4*>(&ra[4]) = *reinterpret_cast<const float4*>(&As[k][64 + ty * 4]);
            *reinterpret_cast<float4*>(&rb[0]) = *reinterpret_cast<const float4*>(&Bs[k][tx * 4]);
            *reinterpret_cast<float4*>(&rb[4]) = *reinterpret_cast<const float4*>(&Bs[k][64 + tx * 4]);
#pragma unroll
            for (int i = 0; i < 8; i++)
#pragma unroll
                for (int j = 0; j < 8; j++)
                    acc[i][j] = fmaf(ra[i], rb[j], acc[i][j]);
        }
        __syncthreads();
    }

#pragma unroll
    for (int i = 0; i < 8; i++) {
        int m = row0 + ((i < 4) ? (ty * 4 + i) : (64 + ty * 4 + (i - 4)));
        if (m >= M) continue;
#pragma unroll
        for (int j = 0; j < 8; j++) {
            int n = col0 + ((j < 4) ? (tx * 4 + j) : (64 + tx * 4 + (j - 4)));
            C[(size_t)m * D_MODEL + n] = acc[i][j] + bias[n];
        }
    }
}

// ---------------------------------------------------------------------------
// Attention kernel: one warp per (b, h, i) row; one LANE per candidate.
// i>0 dist^2 emulates the xor-butterfly reduction order (bit-identical to
// R1's __shfl_xor tree, since fp add is commutative every lane of the
// butterfly holds the same bit pattern).
// ---------------------------------------------------------------------------
__global__ __launch_bounds__(256) void attn_kernel(
    const float* __restrict__ log_sigma,
    float* __restrict__ w_out, float* __restrict__ m_out)
{
    __shared__ __align__(16) float q_sh[8][DK];
    __shared__ float w_sh[8][32];
    __shared__ int   c_sh[8][32];

    int warp = threadIdx.x >> 5;
    int lane = threadIdx.x & 31;
    int rowid = blockIdx.x * 8 + warp;
    if (rowid >= N_ROWS_TOT) return;

    int b   = rowid / (NH * L_SEQ);
    int rem = rowid % (NH * L_SEQ);
    int h   = rem / L_SEQ;
    int i   = rem % L_SEQ;

    float inv = -0.5f * expf(-2.f * log_sigma[0]);   // -0.5 / sigma^2

    const float* qp = g_Q + (size_t)(b * L_SEQ + i) * D_MODEL + h * DK;
    q_sh[warp][lane]      = qp[lane];
    q_sh[warp][lane + 32] = qp[lane + 32];
    __syncwarp();

    float myScore = -INFINITY;
    int   myCol   = 0;
    int   nj;
    bool  act;

    if (i > 0) {
        // Each lane owns one candidate: lane 0 -> CLS, lanes 1.. -> box cells.
        int p = i - 1, r = p / GRID_SZ, c = p % GRID_SZ;
        int r0 = (r - 2 < 0) ? 0 : r - 2;
        int r1 = (r + 2 > GRID_SZ - 1) ? GRID_SZ - 1 : r + 2;
        int c0 = (c - 2 < 0) ? 0 : c - 2;
        int c1 = (c + 2 > GRID_SZ - 1) ? GRID_SZ - 1 : c + 2;
        int wbox = c1 - c0 + 1;
        int hbox = r1 - r0 + 1;
        nj  = 1 + wbox * hbox;
        act = lane < nj;

        int j = 0;
        if (act && lane > 0) {
            int idx = lane - 1;
            j = 1 + (r0 + idx / wbox) * GRID_SZ + (c0 + idx % wbox);
        }

        if (act) {
            const float4* kp4 = reinterpret_cast<const float4*>(
                g_K + (size_t)(b * L_SEQ + j) * D_MODEL + h * DK);
            const float4* qp4 = reinterpret_cast<const float4*>(q_sh[warp]);

            // t[l] = (q[l]-k[l])^2 + (q[l+32]-k[l+32])^2
            float t[32];
#pragma unroll
            for (int g = 0; g < 8; g++) {
                float4 ka = kp4[g];        // dims 4g .. 4g+3
                float4 kb = kp4[g + 8];    // dims 32+4g .. 32+4g+3
                float4 qa = qp4[g];
                float4 qb = qp4[g + 8];
                float d0, d1;
                d0 = qa.x - ka.x; d1 = qb.x - kb.x;
                t[4 * g + 0] = fmaf(d1, d1, d0 * d0);
                d0 = qa.y - ka.y; d1 = qb.y - kb.y;
                t[4 * g + 1] = fmaf(d1, d1, d0 * d0);
                d0 = qa.z - ka.z; d1 = qb.z - kb.z;
                t[4 * g + 2] = fmaf(d1, d1, d0 * d0);
                d0 = qa.w - ka.w; d1 = qb.w - kb.w;
                t[4 * g + 3] = fmaf(d1, d1, d0 * d0);
            }
            // xor-butterfly order: offsets 16, 8, 4, 2, 1
#pragma unroll
            for (int off = 16; off > 0; off >>= 1)
#pragma unroll
                for (int l = 0; l < 16; l++)
                    if (l < off) t[l] += t[l + off];
            myScore = inv * t[0];
            myCol   = j;
        }
    } else {
        // CLS row: 197 candidates, true top-32 (lowest-index tie-break).
        float sc[7];
#pragma unroll
        for (int s = 0; s < 7; s++) {
            int j = s * 32 + lane;
            if (j < L_SEQ) {
                const float4* kp4 = reinterpret_cast<const float4*>(
                    g_K + (size_t)(b * L_SEQ + j) * D_MODEL + h * DK);
                const float4* qp4 = reinterpret_cast<const float4*>(q_sh[warp]);
                float acc = 0.f;
#pragma unroll
                for (int d = 0; d < 16; d++) {
                    float4 kk = kp4[d];
                    float4 qq = qp4[d];
                    float dx = qq.x - kk.x, dy = qq.y - kk.y;
                    float dz = qq.z - kk.z, dw = qq.w - kk.w;
                    acc = fmaf(dx, dx, acc);
                    acc = fmaf(dy, dy, acc);
                    acc = fmaf(dz, dz, acc);
                    acc = fmaf(dw, dw, acc);
                }
                sc[s] = inv * acc;
            } else {
                sc[s] = -INFINITY;
            }
        }

        unsigned used = 0;
        for (int t = 0; t < TOPK; t++) {
            float bv = -INFINITY;
            int   bj = 0x7fffffff;
#pragma unroll
            for (int s = 0; s < 7; s++) {
                if (!((used >> s) & 1u)) {
                    int j = s * 32 + lane;
                    if (sc[s] > bv || (sc[s] == bv && j < bj)) { bv = sc[s]; bj = j; }
                }
            }
#pragma unroll
            for (int o = 16; o > 0; o >>= 1) {
                float ov = __shfl_xor_sync(0xffffffffu, bv, o);
                int   oj = __shfl_xor_sync(0xffffffffu, bj, o);
                if (ov > bv || (ov == bv && oj < bj)) { bv = ov; bj = oj; }
            }
            if (lane == (bj & 31)) used |= 1u << (bj >> 5);  // mark winner consumed
            if (lane == t) { myScore = bv; myCol = bj; }
        }
        nj  = TOPK;
        act = true;
    }

    // Zero-fill dense rows (coalesced)
    float* wrow = w_out + (size_t)rowid * L_SEQ;
    float* mrow = m_out + (size_t)rowid * L_SEQ;
#pragma unroll
    for (int t = lane; t < L_SEQ; t += 32) { wrow[t] = 0.f; mrow[t] = 0.f; }

    // Softmax over active lanes
    float v  = act ? myScore : -INFINITY;
    float mx = v;
#pragma unroll
    for (int o = 16; o > 0; o >>= 1)
        mx = fmaxf(mx, __shfl_xor_sync(0xffffffffu, mx, o));
    float e  = act ? expf(myScore - mx) : 0.f;
    float se = e;
#pragma unroll
    for (int o = 16; o > 0; o >>= 1)
        se += __shfl_xor_sync(0xffffffffu, se, o);
    float w = e / se;

    // Stash weights/cols for consensus
    w_sh[warp][lane] = act ? w : 0.f;
    c_sh[warp][lane] = act ? myCol : 0;
    __syncwarp();

    if (act) {
        wrow[myCol] = w;
        mrow[myCol] = (w > 1e-6f) ? 1.f : 0.f;
    }

    // Consensus: sum_j w_j * V[b,h,j,:]  (lanes index the head dim)
    float a0 = 0.f, a1 = 0.f;
    const float* vbase = g_V + (size_t)b * L_SEQ * D_MODEL + h * DK;
#pragma unroll 4
    for (int t = 0; t < nj; t++) {
        float wv  = w_sh[warp][t];
        int   col = c_sh[warp][t];
        const float* vp = vbase + (size_t)col * D_MODEL;
        a0 = fmaf(wv, vp[lane], a0);
        a1 = fmaf(wv, vp[lane + 32], a1);
    }
    float* cp = g_C + (size_t)(b * L_SEQ + i) * D_MODEL + h * DK;
    cp[lane]      = a0;
    cp[lane + 32] = a1;
}

// ---------------------------------------------------------------------------
extern "C" void kernel_launch(void* const* d_in, const int* in_sizes, int n_in,
                              void* d_out, int out_size)
{
    const float* x  = (const float*)d_in[0];
    const float* Wq = (const float*)d_in[1];
    const float* bq = (const float*)d_in[2];
    const float* Wk = (const float*)d_in[3];
    const float* bk = (const float*)d_in[4];
    const float* Wv = (const float*)d_in[5];
    const float* bv = (const float*)d_in[6];
    const float* Wo = (const float*)d_in[7];
    const float* bo = (const float*)d_in[8];
    const float* ls = (const float*)d_in[9];

    float* out   = (float*)d_out;                                    // (B, L, D)
    float* w_out = out + (size_t)M_ROWS * D_MODEL;                   // (B, H, L, L)
    float* m_out = w_out + (size_t)BATCH * NH * L_SEQ * L_SEQ;       // (B, H, L, L)

    dim3 ggrid(D_MODEL / BN, (M_ROWS + BM - 1) / BM);   // (6, 50)
    dim3 gblk(256);

    // QKV projections (separate launches: measured-good config)
    sgemm_bias<<<ggrid, gblk>>>(x, 0, Wq, bq, nullptr, 0, M_ROWS);
    sgemm_bias<<<ggrid, gblk>>>(x, 0, Wk, bk, nullptr, 1, M_ROWS);
    sgemm_bias<<<ggrid, gblk>>>(x, 0, Wv, bv, nullptr, 2, M_ROWS);

    // Attention (scores + topk + softmax + weights/mask + consensus)
    int nblk = (N_ROWS_TOT + 7) / 8;
    attn_kernel<<<nblk, 256>>>(ls, w_out, m_out);

    // Output projection
    sgemm_bias<<<ggrid, gblk>>>(nullptr, 1, Wo, bo, out, 3, M_ROWS);
}

// round 6
// speedup vs baseline: 1.7136x; 1.0366x over previous
#include <cuda_runtime.h>
#include <math.h>

// Problem constants
#define GRID_SZ 14
#define L_SEQ   197           // 14*14 + 1
#define NH      12
#define DK      64
#define D_MODEL 768
#define BATCH   32
#define M_ROWS  (BATCH * L_SEQ)   // 6304
#define TOPK    32
#define N_ROWS_TOT (BATCH * NH * L_SEQ)  // 75648

// Scratch (device globals: no allocation allowed)
__device__ float g_Q[M_ROWS * D_MODEL];
__device__ float g_K[M_ROWS * D_MODEL];
__device__ float g_V[M_ROWS * D_MODEL];
__device__ float g_C[M_ROWS * D_MODEL];   // consensus (attention output before W_o)

// ---------------------------------------------------------------------------
// SGEMM:  C[M x 768] = A[M x 768] @ B[768 x 768] + bias   (unchanged, passing)
// ---------------------------------------------------------------------------
#define BM 128
#define BN 128
#define BK 8

__global__ __launch_bounds__(256) void sgemm_bias(
    const float* __restrict__ A_ext, int a_sel,
    const float* __restrict__ Bw, const float* __restrict__ bias,
    float* __restrict__ C_ext, int c_sel, int M)
{
    const float* A = (a_sel == 0) ? A_ext : g_C;
    float* C = (c_sel == 0) ? g_Q : (c_sel == 1) ? g_K : (c_sel == 2) ? g_V : C_ext;

    __shared__ __align__(16) float As[BK][BM];
    __shared__ __align__(16) float Bs[BK][BN];

    int bm = blockIdx.y, bn = blockIdx.x;
    int tid = threadIdx.x;
    int tx = tid & 15;
    int ty = tid >> 4;

    float acc[8][8];
#pragma unroll
    for (int i = 0; i < 8; i++)
#pragma unroll
        for (int j = 0; j < 8; j++) acc[i][j] = 0.f;

    int row0 = bm * BM;
    int col0 = bn * BN;

    int a_m = (tid * 4) / BK;
    int a_k = (tid * 4) % BK;
    int b_r = (tid * 4) / BN;
    int b_c = (tid * 4) % BN;

    const int gm = row0 + a_m;
    const bool a_ok = (gm < M);
    const float* Aptr = &A[(size_t)gm * D_MODEL + a_k];
    const float* Bptr = &Bw[(size_t)b_r * D_MODEL + col0 + b_c];

    float4 av = make_float4(0.f, 0.f, 0.f, 0.f);
    if (a_ok) av = *reinterpret_cast<const float4*>(Aptr);
    float4 bv = *reinterpret_cast<const float4*>(Bptr);

    for (int kt = 0; kt < D_MODEL; kt += BK) {
        As[a_k + 0][a_m] = av.x;
        As[a_k + 1][a_m] = av.y;
        As[a_k + 2][a_m] = av.z;
        As[a_k + 3][a_m] = av.w;
        *reinterpret_cast<float4*>(&Bs[b_r][b_c]) = bv;
        __syncthreads();

        if (kt + BK < D_MODEL) {
            if (a_ok) av = *reinterpret_cast<const float4*>(Aptr + kt + BK);
            bv = *reinterpret_cast<const float4*>(Bptr + (size_t)(kt + BK) * D_MODEL);
        }

#pragma unroll
        for (int k = 0; k < BK; k++) {
            float ra[8], rb[8];
            *reinterpret_cast<float4*>(&ra[0]) = *reinterpret_cast<const float4*>(&As[k][ty * 4]);
            *reinterpret_cast<float4*>(&ra[4]) = *reinterpret_cast<const float4*>(&As[k][64 + ty * 4]);
            *reinterpret_cast<float4*>(&rb[0]) = *reinterpret_cast<const float4*>(&Bs[k][tx * 4]);
            *reinterpret_cast<float4*>(&rb[4]) = *reinterpret_cast<const float4*>(&Bs[k][64 + tx * 4]);
#pragma unroll
            for (int i = 0; i < 8; i++)
#pragma unroll
                for (int j = 0; j < 8; j++)
                    acc[i][j] = fmaf(ra[i], rb[j], acc[i][j]);
        }
        __syncthreads();
    }

#pragma unroll
    for (int i = 0; i < 8; i++) {
        int m = row0 + ((i < 4) ? (ty * 4 + i) : (64 + ty * 4 + (i - 4)));
        if (m >= M) continue;
#pragma unroll
        for (int j = 0; j < 8; j++) {
            int n = col0 + ((j < 4) ? (tx * 4 + j) : (64 + tx * 4 + (j - 4)));
            C[(size_t)m * D_MODEL + n] = acc[i][j] + bias[n];
        }
    }
}

// ---------------------------------------------------------------------------
// Attention kernel v2: one BLOCK per (b,h). K slab loaded TRANSPOSED into
// shared memory (Ks_t[d][j], j contiguous) so lane-per-candidate reads at
// fixed d hit distinct banks instead of 32 separate L1 lines.
// Summation orders are bit-identical to the passing R5 kernel:
//   i>0 : t[l] = fmaf(d1,d1,d0*d0) over dim pair (l, l+32), then butterfly
//         tree (offsets 16,8,4,2,1).
//   i==0: sequential d accumulate, then warp top-32.
// ---------------------------------------------------------------------------
__global__ __launch_bounds__(256) void attn_kernel(
    const float* __restrict__ log_sigma,
    float* __restrict__ w_out, float* __restrict__ m_out)
{
    extern __shared__ float Ks_t[];             // [DK][L_SEQ] transposed K slab
    __shared__ float q_sh[8][DK];
    __shared__ float w_sh[8][32];
    __shared__ int   c_sh[8][32];

    int bh   = blockIdx.x;
    int b    = bh / NH;
    int h    = bh % NH;
    int tid  = threadIdx.x;
    int warp = tid >> 5;
    int lane = tid & 31;

    float inv = -0.5f * expf(-2.f * log_sigma[0]);   // -0.5 / sigma^2

    // Cooperative transposed load of K slab: Ks_t[d * L_SEQ + j] = K[b,h,j,d]
    // Write pattern is bank-conflict-free (stride 197*4B, 197*... -> 5d mod 32).
    const float* kslab = g_K + (size_t)b * L_SEQ * D_MODEL + h * DK;
    for (int idx = tid; idx < L_SEQ * DK; idx += 256) {
        int j = idx >> 6;          // 0..196
        int d = idx & 63;          // 0..63
        Ks_t[d * L_SEQ + j] = kslab[(size_t)j * D_MODEL + d];
    }
    __syncthreads();

    const float* vbase = g_V + (size_t)b * L_SEQ * D_MODEL + h * DK;

    for (int i = warp; i < L_SEQ; i += 8) {
        int rowid = (b * NH + h) * L_SEQ + i;

        // Load this row's q into per-warp smem (broadcast source)
        const float* qp = g_Q + (size_t)(b * L_SEQ + i) * D_MODEL + h * DK;
        q_sh[warp][lane]      = qp[lane];
        q_sh[warp][lane + 32] = qp[lane + 32];
        __syncwarp();

        float myScore = -INFINITY;
        int   myCol   = 0;
        int   nj;
        bool  act;

        if (i > 0) {
            // lane 0 -> CLS, lanes 1.. -> box cells (Chebyshev<=2)
            int p = i - 1, r = p / GRID_SZ, c = p % GRID_SZ;
            int r0 = (r - 2 < 0) ? 0 : r - 2;
            int r1 = (r + 2 > GRID_SZ - 1) ? GRID_SZ - 1 : r + 2;
            int c0 = (c - 2 < 0) ? 0 : c - 2;
            int c1 = (c + 2 > GRID_SZ - 1) ? GRID_SZ - 1 : c + 2;
            int wbox = c1 - c0 + 1;
            int hbox = r1 - r0 + 1;
            nj  = 1 + wbox * hbox;
            act = lane < nj;

            int j = 0;
            if (act && lane > 0) {
                int idx = lane - 1;
                j = 1 + (r0 + idx / wbox) * GRID_SZ + (c0 + idx % wbox);
            }

            if (act) {
                float t[32];
#pragma unroll
                for (int d = 0; d < 32; d++) {
                    float qa = q_sh[warp][d];
                    float ka = Ks_t[d * L_SEQ + j];
                    float qb = q_sh[warp][d + 32];
                    float kb = Ks_t[(d + 32) * L_SEQ + j];
                    float d0 = qa - ka;
                    float d1 = qb - kb;
                    t[d] = fmaf(d1, d1, d0 * d0);
                }
                // butterfly bracketing: offsets 16, 8, 4, 2, 1
#pragma unroll
                for (int off = 16; off > 0; off >>= 1)
#pragma unroll
                    for (int l = 0; l < 16; l++)
                        if (l < off) t[l] += t[l + off];
                myScore = inv * t[0];
                myCol   = j;
            }
        } else {
            // CLS row: 197 candidates, true top-32 (lowest-index tie-break)
            float sc[7];
#pragma unroll
            for (int s = 0; s < 7; s++) {
                int j = s * 32 + lane;
                if (j < L_SEQ) {
                    float acc = 0.f;
#pragma unroll
                    for (int d = 0; d < DK; d++) {
                        float df = q_sh[warp][d] - Ks_t[d * L_SEQ + j];
                        acc = fmaf(df, df, acc);
                    }
                    sc[s] = inv * acc;
                } else {
                    sc[s] = -INFINITY;
                }
            }

            unsigned used = 0;
            for (int t = 0; t < TOPK; t++) {
                float bv = -INFINITY;
                int   bj = 0x7fffffff;
#pragma unroll
                for (int s = 0; s < 7; s++) {
                    if (!((used >> s) & 1u)) {
                        int j = s * 32 + lane;
                        if (sc[s] > bv || (sc[s] == bv && j < bj)) { bv = sc[s]; bj = j; }
                    }
                }
#pragma unroll
                for (int o = 16; o > 0; o >>= 1) {
                    float ov = __shfl_xor_sync(0xffffffffu, bv, o);
                    int   oj = __shfl_xor_sync(0xffffffffu, bj, o);
                    if (ov > bv || (ov == bv && oj < bj)) { bv = ov; bj = oj; }
                }
                if (lane == (bj & 31)) used |= 1u << (bj >> 5);
                if (lane == t) { myScore = bv; myCol = bj; }
            }
            nj  = TOPK;
            act = true;
        }

        // Zero-fill dense rows (coalesced)
        float* wrow = w_out + (size_t)rowid * L_SEQ;
        float* mrow = m_out + (size_t)rowid * L_SEQ;
#pragma unroll
        for (int t = lane; t < L_SEQ; t += 32) { wrow[t] = 0.f; mrow[t] = 0.f; }

        // Softmax over active lanes (same shuffle trees as before)
        float v  = act ? myScore : -INFINITY;
        float mx = v;
#pragma unroll
        for (int o = 16; o > 0; o >>= 1)
            mx = fmaxf(mx, __shfl_xor_sync(0xffffffffu, mx, o));
        float e  = act ? expf(myScore - mx) : 0.f;
        float se = e;
#pragma unroll
        for (int o = 16; o > 0; o >>= 1)
            se += __shfl_xor_sync(0xffffffffu, se, o);
        float w = e / se;

        // Stash weights/cols for consensus
        w_sh[warp][lane] = act ? w : 0.f;
        c_sh[warp][lane] = act ? myCol : 0;
        __syncwarp();

        if (act) {
            wrow[myCol] = w;
            mrow[myCol] = (w > 1e-6f) ? 1.f : 0.f;
        }

        // Consensus: sum_j w_j * V[b,h,j,:]  (lanes index the head dim)
        float a0 = 0.f, a1 = 0.f;
#pragma unroll 4
        for (int t = 0; t < nj; t++) {
            float wv  = w_sh[warp][t];
            int   col = c_sh[warp][t];
            const float* vp = vbase + (size_t)col * D_MODEL;
            a0 = fmaf(wv, vp[lane], a0);
            a1 = fmaf(wv, vp[lane + 32], a1);
        }
        float* cp = g_C + (size_t)(b * L_SEQ + i) * D_MODEL + h * DK;
        cp[lane]      = a0;
        cp[lane + 32] = a1;

        __syncwarp();   // protect q_sh / w_sh / c_sh reuse next iteration
    }
}

// ---------------------------------------------------------------------------
extern "C" void kernel_launch(void* const* d_in, const int* in_sizes, int n_in,
                              void* d_out, int out_size)
{
    const float* x  = (const float*)d_in[0];
    const float* Wq = (const float*)d_in[1];
    const float* bq = (const float*)d_in[2];
    const float* Wk = (const float*)d_in[3];
    const float* bk = (const float*)d_in[4];
    const float* Wv = (const float*)d_in[5];
    const float* bv = (const float*)d_in[6];
    const float* Wo = (const float*)d_in[7];
    const float* bo = (const float*)d_in[8];
    const float* ls = (const float*)d_in[9];

    float* out   = (float*)d_out;                                    // (B, L, D)
    float* w_out = out + (size_t)M_ROWS * D_MODEL;                   // (B, H, L, L)
    float* m_out = w_out + (size_t)BATCH * NH * L_SEQ * L_SEQ;       // (B, H, L, L)

    dim3 ggrid(D_MODEL / BN, (M_ROWS + BM - 1) / BM);   // (6, 50)
    dim3 gblk(256);

    // QKV projections
    sgemm_bias<<<ggrid, gblk>>>(x, 0, Wq, bq, nullptr, 0, M_ROWS);
    sgemm_bias<<<ggrid, gblk>>>(x, 0, Wk, bk, nullptr, 1, M_ROWS);
    sgemm_bias<<<ggrid, gblk>>>(x, 0, Wv, bv, nullptr, 2, M_ROWS);

    // Attention: one block per (b,h), K slab in dynamic smem (50.4 KB)
    const int smem_bytes = L_SEQ * DK * (int)sizeof(float);   // 50432
    cudaFuncSetAttribute(attn_kernel, cudaFuncAttributeMaxDynamicSharedMemorySize,
                         smem_bytes);
    attn_kernel<<<BATCH * NH, 256, smem_bytes>>>(ls, w_out, m_out);

    // Output projection
    sgemm_bias<<<ggrid, gblk>>>(nullptr, 1, Wo, bo, out, 3, M_ROWS);
}

// round 8
// speedup vs baseline: 1.7783x; 1.0377x over previous
#include <cuda_runtime.h>
#include <math.h>

// Problem constants
#define GRID_SZ 14
#define L_SEQ   197           // 14*14 + 1
#define NH      12
#define DK      64
#define D_MODEL 768
#define BATCH   32
#define M_ROWS  (BATCH * L_SEQ)   // 6304
#define TOPK    32
#define N_ROWS_TOT (BATCH * NH * L_SEQ)  // 75648
#define ATTN_SPLIT 4

typedef unsigned long long u64;

// Scratch (device globals: no allocation allowed)
__device__ float g_Q[M_ROWS * D_MODEL];
__device__ float g_K[M_ROWS * D_MODEL];
__device__ float g_V[M_ROWS * D_MODEL];
__device__ float g_C[M_ROWS * D_MODEL];   // consensus (attention output before W_o)

// ---- packed f32x2 helpers (sm_103a) ---------------------------------------
__device__ __forceinline__ u64 pack2(float x, float y) {
    u64 r;
    asm("mov.b64 %0, {%1, %2};" : "=l"(r) : "f"(x), "f"(y));
    return r;
}
__device__ __forceinline__ void unpack2(u64 v, float& x, float& y) {
    asm("mov.b64 {%0, %1}, %2;" : "=f"(x), "=f"(y) : "l"(v));
}
__device__ __forceinline__ void ffma2(u64& d, u64 a, u64 b) {
    asm("fma.rn.f32x2 %0, %1, %2, %3;" : "=l"(d) : "l"(a), "l"(b), "l"(d));
}

// ---------------------------------------------------------------------------
// SGEMM:  C[M x 768] = A[M x 768] @ B[768 x 768] + bias
// 128x128 tile, BK=8, 256 threads, 8x8 microtile via packed f32x2 FMA.
// Per-element fmaf chain identical in value/order to the scalar version ->
// bit-identical outputs.
// ---------------------------------------------------------------------------
#define BM 128
#define BN 128
#define BK 8

__global__ __launch_bounds__(256) void sgemm_bias(
    const float* __restrict__ A_ext, int a_sel,
    const float* __restrict__ Bw, const float* __restrict__ bias,
    float* __restrict__ C_ext, int c_sel, int M)
{
    const float* A = (a_sel == 0) ? A_ext : g_C;
    float* C = (c_sel == 0) ? g_Q : (c_sel == 1) ? g_K : (c_sel == 2) ? g_V : C_ext;

    __shared__ __align__(16) float As[BK][BM];
    __shared__ __align__(16) float Bs[BK][BN];

    int bm = blockIdx.y, bn = blockIdx.x;
    int tid = threadIdx.x;
    int tx = tid & 15;
    int ty = tid >> 4;

    u64 acc2[8][4];
#pragma unroll
    for (int i = 0; i < 8; i++)
#pragma unroll
        for (int j = 0; j < 4; j++) acc2[i][j] = 0ull;

    int row0 = bm * BM;
    int col0 = bn * BN;

    int a_m = (tid * 4) / BK;
    int a_k = (tid * 4) % BK;
    int b_r = (tid * 4) / BN;
    int b_c = (tid * 4) % BN;

    const int gm = row0 + a_m;
    const bool a_ok = (gm < M);
    const float* Aptr = &A[(size_t)gm * D_MODEL + a_k];
    const float* Bptr = &Bw[(size_t)b_r * D_MODEL + col0 + b_c];

    float4 av = make_float4(0.f, 0.f, 0.f, 0.f);
    if (a_ok) av = *reinterpret_cast<const float4*>(Aptr);
    float4 bv = *reinterpret_cast<const float4*>(Bptr);

    for (int kt = 0; kt < D_MODEL; kt += BK) {
        As[a_k + 0][a_m] = av.x;
        As[a_k + 1][a_m] = av.y;
        As[a_k + 2][a_m] = av.z;
        As[a_k + 3][a_m] = av.w;
        *reinterpret_cast<float4*>(&Bs[b_r][b_c]) = bv;
        __syncthreads();

        if (kt + BK < D_MODEL) {
            if (a_ok) av = *reinterpret_cast<const float4*>(Aptr + kt + BK);
            bv = *reinterpret_cast<const float4*>(Bptr + (size_t)(kt + BK) * D_MODEL);
        }

#pragma unroll
        for (int k = 0; k < BK; k++) {
            float ra[8];
            *reinterpret_cast<float4*>(&ra[0]) = *reinterpret_cast<const float4*>(&As[k][ty * 4]);
            *reinterpret_cast<float4*>(&ra[4]) = *reinterpret_cast<const float4*>(&As[k][64 + ty * 4]);

            // B fragments arrive pre-packed: LDS.128 viewed as two b64 pairs.
            double2 b01 = *reinterpret_cast<const double2*>(&Bs[k][tx * 4]);
            double2 b23 = *reinterpret_cast<const double2*>(&Bs[k][64 + tx * 4]);
            u64 rb2[4];
            rb2[0] = __double_as_longlong(b01.x);
            rb2[1] = __double_as_longlong(b01.y);
            rb2[2] = __double_as_longlong(b23.x);
            rb2[3] = __double_as_longlong(b23.y);

#pragma unroll
            for (int i = 0; i < 8; i++) {
                u64 ra2 = pack2(ra[i], ra[i]);
#pragma unroll
                for (int j = 0; j < 4; j++)
                    ffma2(acc2[i][j], ra2, rb2[j]);
            }
        }
        __syncthreads();
    }

#pragma unroll
    for (int i = 0; i < 8; i++) {
        int m = row0 + ((i < 4) ? (ty * 4 + i) : (64 + ty * 4 + (i - 4)));
        if (m >= M) continue;
#pragma unroll
        for (int jj = 0; jj < 4; jj++) {
            float lo, hi;
            unpack2(acc2[i][jj], lo, hi);
            int nbase = col0 + ((jj < 2) ? (tx * 4 + 2 * jj) : (64 + tx * 4 + 2 * (jj - 2)));
            C[(size_t)m * D_MODEL + nbase]     = lo + bias[nbase];
            C[(size_t)m * D_MODEL + nbase + 1] = hi + bias[nbase + 1];
        }
    }
}

// ---------------------------------------------------------------------------
// Attention kernel v3: grid (B*NH, ATTN_SPLIT). Each block loads the (b,h)
// K slab transposed into smem and handles rows i = 8*blockIdx.y + warp + 32t.
// All arithmetic/orders identical to the passing R6 kernel.
// ---------------------------------------------------------------------------
__global__ __launch_bounds__(256) void attn_kernel(
    const float* __restrict__ log_sigma,
    float* __restrict__ w_out, float* __restrict__ m_out)
{
    extern __shared__ float Ks_t[];             // [DK][L_SEQ] transposed K slab
    __shared__ float q_sh[8][DK];
    __shared__ float w_sh[8][32];
    __shared__ int   c_sh[8][32];

    int bh   = blockIdx.x;
    int b    = bh / NH;
    int h    = bh % NH;
    int tid  = threadIdx.x;
    int warp = tid >> 5;
    int lane = tid & 31;

    float inv = -0.5f * expf(-2.f * log_sigma[0]);   // -0.5 / sigma^2

    // Cooperative transposed load of K slab: Ks_t[d * L_SEQ + j] = K[b,h,j,d]
    const float* kslab = g_K + (size_t)b * L_SEQ * D_MODEL + h * DK;
    for (int idx = tid; idx < L_SEQ * DK; idx += 256) {
        int j = idx >> 6;          // 0..196
        int d = idx & 63;          // 0..63
        Ks_t[d * L_SEQ + j] = kslab[(size_t)j * D_MODEL + d];
    }
    __syncthreads();

    const float* vbase = g_V + (size_t)b * L_SEQ * D_MODEL + h * DK;

    for (int i = blockIdx.y * 8 + warp; i < L_SEQ; i += 8 * ATTN_SPLIT) {
        int rowid = (b * NH + h) * L_SEQ + i;

        const float* qp = g_Q + (size_t)(b * L_SEQ + i) * D_MODEL + h * DK;
        q_sh[warp][lane]      = qp[lane];
        q_sh[warp][lane + 32] = qp[lane + 32];
        __syncwarp();

        float myScore = -INFINITY;
        int   myCol   = 0;
        int   nj;
        bool  act;

        if (i > 0) {
            // lane 0 -> CLS, lanes 1.. -> box cells (Chebyshev<=2)
            int p = i - 1, r = p / GRID_SZ, c = p % GRID_SZ;
            int r0 = (r - 2 < 0) ? 0 : r - 2;
            int r1 = (r + 2 > GRID_SZ - 1) ? GRID_SZ - 1 : r + 2;
            int c0 = (c - 2 < 0) ? 0 : c - 2;
            int c1 = (c + 2 > GRID_SZ - 1) ? GRID_SZ - 1 : c + 2;
            int wbox = c1 - c0 + 1;
            int hbox = r1 - r0 + 1;
            nj  = 1 + wbox * hbox;
            act = lane < nj;

            int j = 0;
            if (act && lane > 0) {
                int idx = lane - 1;
                j = 1 + (r0 + idx / wbox) * GRID_SZ + (c0 + idx % wbox);
            }

            if (act) {
                float t[32];
#pragma unroll
                for (int d = 0; d < 32; d++) {
                    float qa = q_sh[warp][d];
                    float ka = Ks_t[d * L_SEQ + j];
                    float qb = q_sh[warp][d + 32];
                    float kb = Ks_t[(d + 32) * L_SEQ + j];
                    float d0 = qa - ka;
                    float d1 = qb - kb;
                    t[d] = fmaf(d1, d1, d0 * d0);
                }
                // butterfly bracketing: offsets 16, 8, 4, 2, 1
#pragma unroll
                for (int off = 16; off > 0; off >>= 1)
#pragma unroll
                    for (int l = 0; l < 16; l++)
                        if (l < off) t[l] += t[l + off];
                myScore = inv * t[0];
                myCol   = j;
            }
        } else {
            // CLS row: 197 candidates, true top-32 (lowest-index tie-break)
            float sc[7];
#pragma unroll
            for (int s = 0; s < 7; s++) {
                int j = s * 32 + lane;
                if (j < L_SEQ) {
                    float acc = 0.f;
#pragma unroll
                    for (int d = 0; d < DK; d++) {
                        float df = q_sh[warp][d] - Ks_t[d * L_SEQ + j];
                        acc = fmaf(df, df, acc);
                    }
                    sc[s] = inv * acc;
                } else {
                    sc[s] = -INFINITY;
                }
            }

            unsigned used = 0;
            for (int t = 0; t < TOPK; t++) {
                float bv = -INFINITY;
                int   bj = 0x7fffffff;
#pragma unroll
                for (int s = 0; s < 7; s++) {
                    if (!((used >> s) & 1u)) {
                        int j = s * 32 + lane;
                        if (sc[s] > bv || (sc[s] == bv && j < bj)) { bv = sc[s]; bj = j; }
                    }
                }
#pragma unroll
                for (int o = 16; o > 0; o >>= 1) {
                    float ov = __shfl_xor_sync(0xffffffffu, bv, o);
                    int   oj = __shfl_xor_sync(0xffffffffu, bj, o);
                    if (ov > bv || (ov == bv && oj < bj)) { bv = ov; bj = oj; }
                }
                if (lane == (bj & 31)) used |= 1u << (bj >> 5);
                if (lane == t) { myScore = bv; myCol = bj; }
            }
            nj  = TOPK;
            act = true;
        }

        // Zero-fill dense rows (coalesced)
        float* wrow = w_out + (size_t)rowid * L_SEQ;
        float* mrow = m_out + (size_t)rowid * L_SEQ;
#pragma unroll
        for (int t = lane; t < L_SEQ; t += 32) { wrow[t] = 0.f; mrow[t] = 0.f; }

        // Softmax over active lanes
        float v  = act ? myScore : -INFINITY;
        float mx = v;
#pragma unroll
        for (int o = 16; o > 0; o >>= 1)
            mx = fmaxf(mx, __shfl_xor_sync(0xffffffffu, mx, o));
        float e  = act ? expf(myScore - mx) : 0.f;
        float se = e;
#pragma unroll
        for (int o = 16; o > 0; o >>= 1)
            se += __shfl_xor_sync(0xffffffffu, se, o);
        float w = e / se;

        // Stash weights/cols for consensus
        w_sh[warp][lane] = act ? w : 0.f;
        c_sh[warp][lane] = act ? myCol : 0;
        __syncwarp();

        if (act) {
            wrow[myCol] = w;
            mrow[myCol] = (w > 1e-6f) ? 1.f : 0.f;
        }

        // Consensus: sum_j w_j * V[b,h,j,:]  (lanes index the head dim)
        float a0 = 0.f, a1 = 0.f;
#pragma unroll 4
        for (int t = 0; t < nj; t++) {
            float wv  = w_sh[warp][t];
            int   col = c_sh[warp][t];
            const float* vp = vbase + (size_t)col * D_MODEL;
            a0 = fmaf(wv, vp[lane], a0);
            a1 = fmaf(wv, vp[lane + 32], a1);
        }
        float* cp = g_C + (size_t)(b * L_SEQ + i) * D_MODEL + h * DK;
        cp[lane]      = a0;
        cp[lane + 32] = a1;

        __syncwarp();   // protect q_sh / w_sh / c_sh reuse next iteration
    }
}

// ---------------------------------------------------------------------------
extern "C" void kernel_launch(void* const* d_in, const int* in_sizes, int n_in,
                              void* d_out, int out_size)
{
    const float* x  = (const float*)d_in[0];
    const float* Wq = (const float*)d_in[1];
    const float* bq = (const float*)d_in[2];
    const float* Wk = (const float*)d_in[3];
    const float* bk = (const float*)d_in[4];
    const float* Wv = (const float*)d_in[5];
    const float* bv = (const float*)d_in[6];
    const float* Wo = (const float*)d_in[7];
    const float* bo = (const float*)d_in[8];
    const float* ls = (const float*)d_in[9];

    float* out   = (float*)d_out;                                    // (B, L, D)
    float* w_out = out + (size_t)M_ROWS * D_MODEL;                   // (B, H, L, L)
    float* m_out = w_out + (size_t)BATCH * NH * L_SEQ * L_SEQ;       // (B, H, L, L)

    dim3 ggrid(D_MODEL / BN, (M_ROWS + BM - 1) / BM);   // (6, 50)
    dim3 gblk(256);

    // QKV projections
    sgemm_bias<<<ggrid, gblk>>>(x, 0, Wq, bq, nullptr, 0, M_ROWS);
    sgemm_bias<<<ggrid, gblk>>>(x, 0, Wk, bk, nullptr, 1, M_ROWS);
    sgemm_bias<<<ggrid, gblk>>>(x, 0, Wv, bv, nullptr, 2, M_ROWS);

    // Attention: grid (B*NH, ATTN_SPLIT), K slab in dynamic smem (50.4 KB)
    const int smem_bytes = L_SEQ * DK * (int)sizeof(float);   // 50432
    cudaFuncSetAttribute(attn_kernel, cudaFuncAttributeMaxDynamicSharedMemorySize,
                         smem_bytes);
    dim3 agrid(BATCH * NH, ATTN_SPLIT);
    attn_kernel<<<agrid, 256, smem_bytes>>>(ls, w_out, m_out);

    // Output projection
    sgemm_bias<<<ggrid, gblk>>>(nullptr, 1, Wo, bo, out, 3, M_ROWS);
}